// round 14
// baseline (speedup 1.0000x reference)
#include <cuda_runtime.h>
#include <cuda_fp16.h>
#include <cstdint>
#include <cstddef>

#define N_NODES 8192
#define F_DIM 512
#define UNITS 256
#define N_GATHER 4096
#define SPLITS 8

// Device-global scratch (no allocation allowed)
__device__ __align__(16) float  g_d[N_NODES];                    // 32 KB
__device__ __align__(16) float  g_y32[N_NODES * UNITS];          // 8 MB
__device__ __align__(16) __half g_y16[N_NODES * UNITS];          // 4 MB
__device__ __align__(16) __half g_f16[N_NODES * F_DIM];          // 8 MB
__device__ __align__(16) __half g_w16[F_DIM * UNITS];            // 256 KB
__device__ __align__(16) __half g_adj16[(size_t)N_NODES * N_NODES]; // 128 MB
__device__ __align__(16) float  g_part[(size_t)SPLITS * N_GATHER * UNITS]; // 32 MB
__device__ __align__(16) int    g_idx[N_GATHER];
__device__               int    g_rowflag[N_NODES];

// ---------------------------------------------------------------------------
// helpers
// ---------------------------------------------------------------------------
__device__ __forceinline__ uint32_t f2h2(float a, float b)
{
    __half2 h = __floats2half2_rn(a, b);
    return *reinterpret_cast<uint32_t*>(&h);
}
__device__ __forceinline__ uint32_t smem_u32(const void* p)
{
    return (uint32_t)__cvta_generic_to_shared(p);
}
__device__ __forceinline__ void cp16(void* sdst, const void* gsrc)
{
    asm volatile("cp.async.cg.shared.global [%0], [%1], 16;"
                 :: "r"(smem_u32(sdst)), "l"(gsrc));
}
#define CP_COMMIT() asm volatile("cp.async.commit_group;" ::)
#define CP_WAIT(n)  asm volatile("cp.async.wait_group %0;" :: "n"(n))

__device__ __forceinline__ void ldsm_x4(uint32_t& r0, uint32_t& r1, uint32_t& r2, uint32_t& r3,
                                        uint32_t a)
{
    asm volatile("ldmatrix.sync.aligned.m8n8.x4.shared.b16 {%0,%1,%2,%3}, [%4];"
                 : "=r"(r0), "=r"(r1), "=r"(r2), "=r"(r3) : "r"(a));
}
__device__ __forceinline__ void ldsm_x4_t(uint32_t& r0, uint32_t& r1, uint32_t& r2, uint32_t& r3,
                                          uint32_t a)
{
    asm volatile("ldmatrix.sync.aligned.m8n8.x4.trans.shared.b16 {%0,%1,%2,%3}, [%4];"
                 : "=r"(r0), "=r"(r1), "=r"(r2), "=r"(r3) : "r"(a));
}
__device__ __forceinline__ void mma16816(float* c,
                                         uint32_t a0, uint32_t a1, uint32_t a2, uint32_t a3,
                                         uint32_t b0, uint32_t b1)
{
    asm volatile(
        "mma.sync.aligned.m16n8k16.row.col.f32.f16.f16.f32 "
        "{%0,%1,%2,%3}, {%4,%5,%6,%7}, {%8,%9}, {%0,%1,%2,%3};"
        : "+f"(c[0]), "+f"(c[1]), "+f"(c[2]), "+f"(c[3])
        : "r"(a0), "r"(a1), "r"(a2), "r"(a3), "r"(b0), "r"(b1));
}

// ---------------------------------------------------------------------------
// K0: dtype-agnostic gather expansion + gathered-row bitmap.
// ---------------------------------------------------------------------------
__global__ void __launch_bounds__(256) k_gather_prep(const int* __restrict__ gather_raw)
{
    for (int r = threadIdx.x; r < N_NODES; r += 256) g_rowflag[r] = 0;
    __syncthreads();

    __shared__ int is64;
    if (threadIdx.x == 0) {
        int odd_or = 0;
#pragma unroll
        for (int w = 1; w < 16; w += 2) odd_or |= gather_raw[w];
        is64 = (odd_or == 0) ? 1 : 0;
    }
    __syncthreads();
    const int w64 = is64;
    for (int g = threadIdx.x; g < N_GATHER; g += 256) {
        int idx = w64 ? gather_raw[g * 2] : gather_raw[g];
        idx = idx < 0 ? 0 : (idx >= N_NODES ? N_NODES - 1 : idx);
        g_idx[g] = idx;
        g_rowflag[idx] = 1;
    }
}

// ---------------------------------------------------------------------------
// K0b: transcode features and kernel to fp16.
// ---------------------------------------------------------------------------
__global__ void __launch_bounds__(256) k_cvt(const float* __restrict__ feat,
                                             const float* __restrict__ wk)
{
    int b = blockIdx.x;
    if (b < 4096) {
        int base = b * 1024 + threadIdx.x * 4;
        float4 v = *reinterpret_cast<const float4*>(feat + base);
        uint2 w;
        w.x = f2h2(v.x, v.y);
        w.y = f2h2(v.z, v.w);
        *reinterpret_cast<uint2*>(&g_f16[base]) = w;
    } else {
        int base = (b - 4096) * 1024 + threadIdx.x * 4;
        float4 v = *reinterpret_cast<const float4*>(wk + base);
        uint2 w;
        w.x = f2h2(v.x, v.y);
        w.y = f2h2(v.z, v.w);
        *reinterpret_cast<uint2*>(&g_w16[base]) = w;
    }
}

// ---------------------------------------------------------------------------
// K1: rowsum -> d[i] = rsqrt(sum+1); fp16 transcode ONLY for gathered rows.
// ---------------------------------------------------------------------------
__global__ void __launch_bounds__(256) k_rowsum16(const float* __restrict__ adj)
{
    const int row = blockIdx.x;
    const bool wr = (g_rowflag[row] != 0);
    const float4* p = reinterpret_cast<const float4*>(adj + (size_t)row * N_NODES);
    uint2* q = reinterpret_cast<uint2*>(&g_adj16[(size_t)row * N_NODES]);
    float s = 0.f;
    if (wr) {
#pragma unroll 4
        for (int j = threadIdx.x; j < N_NODES / 4; j += 256) {
            float4 v = p[j];
            s += (v.x + v.y) + (v.z + v.w);
            uint2 w;
            w.x = f2h2(v.x, v.y);
            w.y = f2h2(v.z, v.w);
            q[j] = w;
        }
    } else {
#pragma unroll 4
        for (int j = threadIdx.x; j < N_NODES / 4; j += 256) {
            float4 v = p[j];
            s += (v.x + v.y) + (v.z + v.w);
        }
    }
#pragma unroll
    for (int o = 16; o > 0; o >>= 1) s += __shfl_xor_sync(0xffffffffu, s, o);
    __shared__ float ws[8];
    if ((threadIdx.x & 31) == 0) ws[threadIdx.x >> 5] = s;
    __syncthreads();
    if (threadIdx.x == 0) {
        float t = 0.f;
#pragma unroll
        for (int w = 0; w < 8; w++) t += ws[w];
        g_d[row] = rsqrtf(t + 1.0f);
    }
}

// ---------------------------------------------------------------------------
// K2 geometry: BM=64, BN=64, BK=64, 128 threads, 2-stage.
// ---------------------------------------------------------------------------
#define GBM 64
#define GBN 64
#define GBK 64
#define GSTG 2
#define GAS 72
#define GBS 72

#define GEMM_COMPUTE(As_, Bs_, s_)                                                  \
    _Pragma("unroll")                                                               \
    for (int ks = 0; ks < 4; ++ks) {                                                \
        uint32_t af[2][4], bf[2][4];                                                \
        _Pragma("unroll")                                                           \
        for (int mf = 0; mf < 2; mf++) {                                            \
            int r = warpM * 32 + mf * 16 + (lane & 15);                             \
            int c = ks * 16 + ((lane >> 4) << 3);                                   \
            ldsm_x4(af[mf][0], af[mf][1], af[mf][2], af[mf][3],                     \
                    smem_u32(&As_[s_][r][c]));                                      \
        }                                                                           \
        _Pragma("unroll")                                                           \
        for (int ng = 0; ng < 2; ng++) {                                            \
            int r = ks * 16 + (lane & 15);                                          \
            int c = warpN * 32 + ng * 16 + ((lane >> 4) << 3);                      \
            ldsm_x4_t(bf[ng][0], bf[ng][1], bf[ng][2], bf[ng][3],                   \
                      smem_u32(&Bs_[s_][r][c]));                                    \
        }                                                                           \
        _Pragma("unroll")                                                           \
        for (int mf = 0; mf < 2; mf++)                                              \
            _Pragma("unroll")                                                       \
            for (int nf = 0; nf < 4; nf++)                                          \
                mma16816(acc[mf][nf],                                               \
                         af[mf][0], af[mf][1], af[mf][2], af[mf][3],                \
                         bf[nf >> 1][(nf & 1) * 2], bf[nf >> 1][(nf & 1) * 2 + 1]); \
    }

#define GEMM_MAINLOOP(KT_)                                                          \
    load_stage(0, 0);                                                               \
    CP_COMMIT();                                                                    \
    for (int kt = 0; kt < (KT_); ++kt) {                                            \
        __syncthreads();                                                            \
        if (kt + 1 < (KT_)) load_stage(kt + 1, (kt + 1) & 1);                       \
        CP_COMMIT();                                                                \
        CP_WAIT(1);                                                                 \
        __syncthreads();                                                            \
        GEMM_COMPUTE(As, Bs, kt & 1);                                               \
    }

// ---------------------------------------------------------------------------
// K2: y = diag(d) * (f16 @ w16)  -> g_y32 + g_y16.  KT = 8.
// ---------------------------------------------------------------------------
__global__ void __launch_bounds__(128) k_xw16()
{
    __shared__ __align__(16) __half As[GSTG][GBM][GAS];
    __shared__ __align__(16) __half Bs[GSTG][GBK][GBS];

    const int tid   = threadIdx.x;
    const int lane  = tid & 31;
    const int warp  = tid >> 5;
    const int warpM = warp >> 1;
    const int warpN = warp & 1;
    const int r0 = blockIdx.x * GBM;
    const int c0 = blockIdx.y * GBN;
    const int KT = F_DIM / GBK;   // 8

    const int lr = tid >> 3;
    const int lc = (tid & 7) * 8;

    auto load_stage = [&](int kt, int s) {
        const int k0 = kt * GBK;
#pragma unroll
        for (int p = 0; p < 4; p++) {
            int row = lr + p * 16;
            cp16(&As[s][row][lc], g_f16 + (size_t)(r0 + row) * F_DIM + k0 + lc);
        }
#pragma unroll
        for (int p = 0; p < 4; p++) {
            int row = lr + p * 16;
            cp16(&Bs[s][row][lc], g_w16 + (size_t)(k0 + row) * UNITS + c0 + lc);
        }
    };

    float acc[2][4][4];
#pragma unroll
    for (int mf = 0; mf < 2; mf++)
#pragma unroll
        for (int nf = 0; nf < 4; nf++)
#pragma unroll
            for (int e = 0; e < 4; e++) acc[mf][nf][e] = 0.f;

    GEMM_MAINLOOP(KT)

    const int groupID = lane >> 2;
    const int tid4    = lane & 3;
#pragma unroll
    for (int mf = 0; mf < 2; mf++) {
#pragma unroll
        for (int nf = 0; nf < 4; nf++) {
            int c = c0 + warpN * 32 + nf * 8 + tid4 * 2;
#pragma unroll
            for (int h = 0; h < 2; h++) {
                int r = r0 + warpM * 32 + mf * 16 + groupID + h * 8;
                float dr = g_d[r];
                float v0 = dr * acc[mf][nf][h * 2 + 0];
                float v1 = dr * acc[mf][nf][h * 2 + 1];
                g_y32[(size_t)r * UNITS + c]     = v0;
                g_y32[(size_t)r * UNITS + c + 1] = v1;
                *reinterpret_cast<uint32_t*>(&g_y16[(size_t)r * UNITS + c]) = f2h2(v0, v1);
            }
        }
    }
}

// ---------------------------------------------------------------------------
// K3: split-K partial GEMM, FULL-N CTAs (each adj row loaded once chip-wide).
// BM=64 x BN=256 x BK=32, 256 threads / 8 warps (warp tile 32x64), 2-stage.
// grid (64, 1, SPLITS).  KT per split = 8192/32/8 = 32.
// smem = 2*(64*40 + 32*264)*2B = 44 KB.
// ---------------------------------------------------------------------------
#define SBM 64
#define SBN 256
#define SBK 32
#define SAS 40    // A row stride (halves)
#define SBS 264   // B row stride (halves)

__global__ void __launch_bounds__(256, 2) k_spmm16_split()
{
    __shared__ __align__(16) __half As[2][SBM][SAS];
    __shared__ __align__(16) __half Bs[2][SBK][SBS];
    __shared__ int rowIdx[SBM];

    const int tid   = threadIdx.x;
    const int lane  = tid & 31;
    const int warp  = tid >> 5;
    const int warpM = warp >> 2;      // 0..1
    const int warpN = warp & 3;       // 0..3
    const int m0 = blockIdx.x * SBM;
    const int z  = blockIdx.z;
    const int KT = N_NODES / SBK / SPLITS;   // 32
    const int kbase = z * KT;

    if (tid < SBM) rowIdx[tid] = g_idx[m0 + tid];
    __syncthreads();

    // A loader: 1 chunk/thread. row = tid>>2 (0..63), col = (tid&3)*8
    const int aRow = tid >> 2;
    const int aCol = (tid & 3) * 8;
    const __half* aSrc = g_adj16 + (size_t)rowIdx[aRow] * N_NODES + aCol;

    auto load_stage = [&](int kt, int s) {
        const int k0 = (kbase + kt) * SBK;
        cp16(&As[s][aRow][aCol], aSrc + k0);
        // B loader: 4 chunks/thread. chunk = tid*4+j; row = chunk>>5, col = (chunk&31)*8
#pragma unroll
        for (int j = 0; j < 4; j++) {
            int chunk = tid * 4 + j;
            int br = chunk >> 5;
            int bc = (chunk & 31) * 8;
            cp16(&Bs[s][br][bc], g_y16 + (size_t)(k0 + br) * UNITS + bc);
        }
    };

    float acc[2][8][4];
#pragma unroll
    for (int mf = 0; mf < 2; mf++)
#pragma unroll
        for (int nf = 0; nf < 8; nf++)
#pragma unroll
            for (int e = 0; e < 4; e++) acc[mf][nf][e] = 0.f;

    load_stage(0, 0);
    CP_COMMIT();
    for (int kt = 0; kt < KT; ++kt) {
        __syncthreads();
        if (kt + 1 < KT) load_stage(kt + 1, (kt + 1) & 1);
        CP_COMMIT();
        CP_WAIT(1);
        __syncthreads();
        const int s = kt & 1;
#pragma unroll
        for (int ks = 0; ks < 2; ++ks) {
            uint32_t af[2][4], bf[4][4];
#pragma unroll
            for (int mf = 0; mf < 2; mf++) {
                int r = warpM * 32 + mf * 16 + (lane & 15);
                int c = ks * 16 + ((lane >> 4) << 3);
                ldsm_x4(af[mf][0], af[mf][1], af[mf][2], af[mf][3],
                        smem_u32(&As[s][r][c]));
            }
#pragma unroll
            for (int ng = 0; ng < 4; ng++) {
                int r = ks * 16 + (lane & 15);
                int c = warpN * 64 + ng * 16 + ((lane >> 4) << 3);
                ldsm_x4_t(bf[ng][0], bf[ng][1], bf[ng][2], bf[ng][3],
                          smem_u32(&Bs[s][r][c]));
            }
#pragma unroll
            for (int mf = 0; mf < 2; mf++)
#pragma unroll
                for (int nf = 0; nf < 8; nf++)
                    mma16816(acc[mf][nf],
                             af[mf][0], af[mf][1], af[mf][2], af[mf][3],
                             bf[nf >> 1][(nf & 1) * 2], bf[nf >> 1][(nf & 1) * 2 + 1]);
        }
    }

    // write raw partials
    float* part = g_part + (size_t)z * N_GATHER * UNITS;
    const int groupID = lane >> 2;
    const int tid4    = lane & 3;
#pragma unroll
    for (int mf = 0; mf < 2; mf++) {
#pragma unroll
        for (int nf = 0; nf < 8; nf++) {
            int c = warpN * 64 + nf * 8 + tid4 * 2;
#pragma unroll
            for (int h = 0; h < 2; h++) {
                int g = m0 + warpM * 32 + mf * 16 + groupID + h * 8;
                part[(size_t)g * UNITS + c]     = acc[mf][nf][h * 2 + 0];
                part[(size_t)g * UNITS + c + 1] = acc[mf][nf][h * 2 + 1];
            }
        }
    }
}

// ---------------------------------------------------------------------------
// K4: reduce splits + epilogue.
// out[g,c] = relu( d_i * ( sum_z part[z][g][c] + y32[i][c] ) + bias[c] )
// ---------------------------------------------------------------------------
__global__ void __launch_bounds__(256) k_reduce(const float* __restrict__ bias,
                                                float* __restrict__ out)
{
    const int t  = blockIdx.x * 256 + threadIdx.x;   // 0 .. 4096*64-1
    const int g  = t >> 6;
    const int c  = (t & 63) * 4;
    const int i  = g_idx[g];
    const float di = g_d[i];

    float4 s = *reinterpret_cast<const float4*>(&g_part[(size_t)g * UNITS + c]);
#pragma unroll
    for (int z = 1; z < SPLITS; z++) {
        const float4 p = *reinterpret_cast<const float4*>(
            &g_part[(size_t)z * N_GATHER * UNITS + (size_t)g * UNITS + c]);
        s.x += p.x; s.y += p.y; s.z += p.z; s.w += p.w;
    }
    const float4 y = *reinterpret_cast<const float4*>(&g_y32[(size_t)i * UNITS + c]);
    const float4 b = *reinterpret_cast<const float4*>(&bias[c]);

    float4 r;
    r.x = fmaxf(di * (s.x + y.x) + b.x, 0.f);
    r.y = fmaxf(di * (s.y + y.y) + b.y, 0.f);
    r.z = fmaxf(di * (s.z + y.z) + b.z, 0.f);
    r.w = fmaxf(di * (s.w + y.w) + b.w, 0.f);
    *reinterpret_cast<float4*>(&out[(size_t)g * UNITS + c]) = r;
}

// ---------------------------------------------------------------------------
// Launch — inputs resolved BY ELEMENT COUNT (order-proof)
// ---------------------------------------------------------------------------
extern "C" void kernel_launch(void* const* d_in, const int* in_sizes, int n_in,
                              void* d_out, int out_size)
{
    (void)out_size;
    const float* adj    = nullptr;
    const int*   gather = nullptr;
    const float* feat   = nullptr;
    const float* wk     = nullptr;
    const float* bias   = nullptr;

    for (int i = 0; i < n_in; i++) {
        switch (in_sizes[i]) {
            case 67108864: adj    = (const float*)d_in[i]; break;
            case 4096:     gather = (const int*)d_in[i];   break;
            case 4194304:  feat   = (const float*)d_in[i]; break;
            case 131072:   wk     = (const float*)d_in[i]; break;
            case 256:      bias   = (const float*)d_in[i]; break;
            default: break;
        }
    }
    float* out = (float*)d_out;

    k_gather_prep<<<1, 256>>>(gather);
    k_cvt<<<4096 + 128, 256>>>(feat, wk);
    k_rowsum16<<<N_NODES, 256>>>(adj);
    k_xw16<<<dim3(N_NODES / GBM, UNITS / GBN), 128>>>();
    k_spmm16_split<<<dim3(N_GATHER / SBM, 1, SPLITS), 256>>>();
    k_reduce<<<(N_GATHER * UNITS / 4) / 256, 256>>>(bias, out);
}

// round 15
// speedup vs baseline: 1.0934x; 1.0934x over previous
#include <cuda_runtime.h>
#include <cuda_fp16.h>
#include <cstdint>
#include <cstddef>

#define N_NODES 8192
#define F_DIM 512
#define UNITS 256
#define N_GATHER 4096
#define SPLITS 4

// Device-global scratch (no allocation allowed)
__device__ __align__(16) float  g_d[N_NODES];                    // 32 KB
__device__ __align__(16) float  g_y32[N_NODES * UNITS];          // 8 MB
__device__ __align__(16) __half g_y16[N_NODES * UNITS];          // 4 MB
__device__ __align__(16) __half g_f16[N_NODES * F_DIM];          // 8 MB
__device__ __align__(16) __half g_w16[F_DIM * UNITS];            // 256 KB
__device__ __align__(16) __half g_adj16[(size_t)N_NODES * N_NODES]; // 128 MB
__device__ __align__(16) float  g_part[(size_t)SPLITS * N_GATHER * UNITS]; // 16 MB
__device__ __align__(16) int    g_idx[N_GATHER];
__device__               int    g_rowflag[N_NODES];

// ---------------------------------------------------------------------------
// helpers
// ---------------------------------------------------------------------------
__device__ __forceinline__ uint32_t f2h2(float a, float b)
{
    __half2 h = __floats2half2_rn(a, b);
    return *reinterpret_cast<uint32_t*>(&h);
}
__device__ __forceinline__ uint32_t smem_u32(const void* p)
{
    return (uint32_t)__cvta_generic_to_shared(p);
}
__device__ __forceinline__ void cp16(void* sdst, const void* gsrc)
{
    asm volatile("cp.async.cg.shared.global [%0], [%1], 16;"
                 :: "r"(smem_u32(sdst)), "l"(gsrc));
}
#define CP_COMMIT() asm volatile("cp.async.commit_group;" ::)
#define CP_WAIT(n)  asm volatile("cp.async.wait_group %0;" :: "n"(n))

__device__ __forceinline__ void ldsm_x4(uint32_t& r0, uint32_t& r1, uint32_t& r2, uint32_t& r3,
                                        uint32_t a)
{
    asm volatile("ldmatrix.sync.aligned.m8n8.x4.shared.b16 {%0,%1,%2,%3}, [%4];"
                 : "=r"(r0), "=r"(r1), "=r"(r2), "=r"(r3) : "r"(a));
}
__device__ __forceinline__ void ldsm_x4_t(uint32_t& r0, uint32_t& r1, uint32_t& r2, uint32_t& r3,
                                          uint32_t a)
{
    asm volatile("ldmatrix.sync.aligned.m8n8.x4.trans.shared.b16 {%0,%1,%2,%3}, [%4];"
                 : "=r"(r0), "=r"(r1), "=r"(r2), "=r"(r3) : "r"(a));
}
__device__ __forceinline__ void mma16816(float* c,
                                         uint32_t a0, uint32_t a1, uint32_t a2, uint32_t a3,
                                         uint32_t b0, uint32_t b1)
{
    asm volatile(
        "mma.sync.aligned.m16n8k16.row.col.f32.f16.f16.f32 "
        "{%0,%1,%2,%3}, {%4,%5,%6,%7}, {%8,%9}, {%0,%1,%2,%3};"
        : "+f"(c[0]), "+f"(c[1]), "+f"(c[2]), "+f"(c[3])
        : "r"(a0), "r"(a1), "r"(a2), "r"(a3), "r"(b0), "r"(b1));
}

// ---------------------------------------------------------------------------
// K0: dtype-agnostic gather expansion + gathered-row bitmap.
// ---------------------------------------------------------------------------
__global__ void __launch_bounds__(256) k_gather_prep(const int* __restrict__ gather_raw)
{
    for (int r = threadIdx.x; r < N_NODES; r += 256) g_rowflag[r] = 0;
    __syncthreads();

    __shared__ int is64;
    if (threadIdx.x == 0) {
        int odd_or = 0;
#pragma unroll
        for (int w = 1; w < 16; w += 2) odd_or |= gather_raw[w];
        is64 = (odd_or == 0) ? 1 : 0;
    }
    __syncthreads();
    const int w64 = is64;
    for (int g = threadIdx.x; g < N_GATHER; g += 256) {
        int idx = w64 ? gather_raw[g * 2] : gather_raw[g];
        idx = idx < 0 ? 0 : (idx >= N_NODES ? N_NODES - 1 : idx);
        g_idx[g] = idx;
        g_rowflag[idx] = 1;
    }
}

// ---------------------------------------------------------------------------
// K0b: transcode features and kernel to fp16.
// ---------------------------------------------------------------------------
__global__ void __launch_bounds__(256) k_cvt(const float* __restrict__ feat,
                                             const float* __restrict__ wk)
{
    int b = blockIdx.x;
    if (b < 4096) {
        int base = b * 1024 + threadIdx.x * 4;
        float4 v = *reinterpret_cast<const float4*>(feat + base);
        uint2 w;
        w.x = f2h2(v.x, v.y);
        w.y = f2h2(v.z, v.w);
        *reinterpret_cast<uint2*>(&g_f16[base]) = w;
    } else {
        int base = (b - 4096) * 1024 + threadIdx.x * 4;
        float4 v = *reinterpret_cast<const float4*>(wk + base);
        uint2 w;
        w.x = f2h2(v.x, v.y);
        w.y = f2h2(v.z, v.w);
        *reinterpret_cast<uint2*>(&g_w16[base]) = w;
    }
}

// ---------------------------------------------------------------------------
// K1: rowsum -> d[i] = rsqrt(sum+1); fp16 transcode ONLY for gathered rows.
// ---------------------------------------------------------------------------
__global__ void __launch_bounds__(256) k_rowsum16(const float* __restrict__ adj)
{
    const int row = blockIdx.x;
    const bool wr = (g_rowflag[row] != 0);
    const float4* p = reinterpret_cast<const float4*>(adj + (size_t)row * N_NODES);
    uint2* q = reinterpret_cast<uint2*>(&g_adj16[(size_t)row * N_NODES]);
    float s = 0.f;
    if (wr) {
#pragma unroll 4
        for (int j = threadIdx.x; j < N_NODES / 4; j += 256) {
            float4 v = p[j];
            s += (v.x + v.y) + (v.z + v.w);
            uint2 w;
            w.x = f2h2(v.x, v.y);
            w.y = f2h2(v.z, v.w);
            q[j] = w;
        }
    } else {
#pragma unroll 4
        for (int j = threadIdx.x; j < N_NODES / 4; j += 256) {
            float4 v = p[j];
            s += (v.x + v.y) + (v.z + v.w);
        }
    }
#pragma unroll
    for (int o = 16; o > 0; o >>= 1) s += __shfl_xor_sync(0xffffffffu, s, o);
    __shared__ float ws[8];
    if ((threadIdx.x & 31) == 0) ws[threadIdx.x >> 5] = s;
    __syncthreads();
    if (threadIdx.x == 0) {
        float t = 0.f;
#pragma unroll
        for (int w = 0; w < 8; w++) t += ws[w];
        g_d[row] = rsqrtf(t + 1.0f);
    }
}

// ---------------------------------------------------------------------------
// K2 geometry: BM=64, BN=64, BK=64, 128 threads, 2-stage.  (unchanged, 16 µs)
// ---------------------------------------------------------------------------
#define GBM 64
#define GBN 64
#define GBK 64
#define GSTG 2
#define GAS 72
#define GBS 72

#define GEMM_COMPUTE(As_, Bs_, s_, KSN_)                                            \
    _Pragma("unroll")                                                               \
    for (int ks = 0; ks < (KSN_); ++ks) {                                           \
        uint32_t af[2][4], bf[2][4];                                                \
        _Pragma("unroll")                                                           \
        for (int mf = 0; mf < 2; mf++) {                                            \
            int r = warpM * 32 + mf * 16 + (lane & 15);                             \
            int c = ks * 16 + ((lane >> 4) << 3);                                   \
            ldsm_x4(af[mf][0], af[mf][1], af[mf][2], af[mf][3],                     \
                    smem_u32(&As_[s_][r][c]));                                      \
        }                                                                           \
        _Pragma("unroll")                                                           \
        for (int ng = 0; ng < 2; ng++) {                                            \
            int r = ks * 16 + (lane & 15);                                          \
            int c = warpN * 32 + ng * 16 + ((lane >> 4) << 3);                      \
            ldsm_x4_t(bf[ng][0], bf[ng][1], bf[ng][2], bf[ng][3],                   \
                      smem_u32(&Bs_[s_][r][c]));                                    \
        }                                                                           \
        _Pragma("unroll")                                                           \
        for (int mf = 0; mf < 2; mf++)                                              \
            _Pragma("unroll")                                                       \
            for (int nf = 0; nf < 4; nf++)                                          \
                mma16816(acc[mf][nf],                                               \
                         af[mf][0], af[mf][1], af[mf][2], af[mf][3],                \
                         bf[nf >> 1][(nf & 1) * 2], bf[nf >> 1][(nf & 1) * 2 + 1]); \
    }

// ---------------------------------------------------------------------------
// K2: y = diag(d) * (f16 @ w16)  -> g_y32 + g_y16.  KT = 8.
// ---------------------------------------------------------------------------
__global__ void __launch_bounds__(128) k_xw16()
{
    __shared__ __align__(16) __half As[GSTG][GBM][GAS];
    __shared__ __align__(16) __half Bs[GSTG][GBK][GBS];

    const int tid   = threadIdx.x;
    const int lane  = tid & 31;
    const int warp  = tid >> 5;
    const int warpM = warp >> 1;
    const int warpN = warp & 1;
    const int r0 = blockIdx.x * GBM;
    const int c0 = blockIdx.y * GBN;
    const int KT = F_DIM / GBK;   // 8

    const int lr = tid >> 3;
    const int lc = (tid & 7) * 8;

    auto load_stage = [&](int kt, int s) {
        const int k0 = kt * GBK;
#pragma unroll
        for (int p = 0; p < 4; p++) {
            int row = lr + p * 16;
            cp16(&As[s][row][lc], g_f16 + (size_t)(r0 + row) * F_DIM + k0 + lc);
        }
#pragma unroll
        for (int p = 0; p < 4; p++) {
            int row = lr + p * 16;
            cp16(&Bs[s][row][lc], g_w16 + (size_t)(k0 + row) * UNITS + c0 + lc);
        }
    };

    float acc[2][4][4];
#pragma unroll
    for (int mf = 0; mf < 2; mf++)
#pragma unroll
        for (int nf = 0; nf < 4; nf++)
#pragma unroll
            for (int e = 0; e < 4; e++) acc[mf][nf][e] = 0.f;

    load_stage(0, 0);
    CP_COMMIT();
    for (int kt = 0; kt < KT; ++kt) {
        __syncthreads();
        if (kt + 1 < KT) load_stage(kt + 1, (kt + 1) & 1);
        CP_COMMIT();
        CP_WAIT(1);
        __syncthreads();
        GEMM_COMPUTE(As, Bs, kt & 1, 4)
    }

    const int groupID = lane >> 2;
    const int tid4    = lane & 3;
#pragma unroll
    for (int mf = 0; mf < 2; mf++) {
#pragma unroll
        for (int nf = 0; nf < 4; nf++) {
            int c = c0 + warpN * 32 + nf * 8 + tid4 * 2;
#pragma unroll
            for (int h = 0; h < 2; h++) {
                int r = r0 + warpM * 32 + mf * 16 + groupID + h * 8;
                float dr = g_d[r];
                float v0 = dr * acc[mf][nf][h * 2 + 0];
                float v1 = dr * acc[mf][nf][h * 2 + 1];
                g_y32[(size_t)r * UNITS + c]     = v0;
                g_y32[(size_t)r * UNITS + c + 1] = v1;
                *reinterpret_cast<uint32_t*>(&g_y16[(size_t)r * UNITS + c]) = f2h2(v0, v1);
            }
        }
    }
}

// ---------------------------------------------------------------------------
// K3: split-K partial GEMM.  BM=64 x BN=64 x BK=32, 128 threads / 4 warps,
// 3-stage cp.async pipeline (2-deep lookahead).  grid (64, 4, SPLITS).
// KT per split = 8192/32/4 = 64.  smem = 3*(64*40 + 32*72)*2B = 28.9 KB.
// ---------------------------------------------------------------------------
#define SBM 64
#define SBN 64
#define SBK 32
#define SSTG 3
#define SAS 40    // A row stride (halves)
#define SBS 72    // B row stride (halves)

__global__ void __launch_bounds__(128) k_spmm16_split()
{
    __shared__ __align__(16) __half As[SSTG][SBM][SAS];
    __shared__ __align__(16) __half Bs[SSTG][SBK][SBS];
    __shared__ int rowIdx[SBM];

    const int tid   = threadIdx.x;
    const int lane  = tid & 31;
    const int warp  = tid >> 5;
    const int warpM = warp >> 1;      // 0..1
    const int warpN = warp & 1;       // 0..1
    const int m0 = blockIdx.x * SBM;
    const int n0 = blockIdx.y * SBN;
    const int z  = blockIdx.z;
    const int KT = N_NODES / SBK / SPLITS;   // 64
    const int kbase = z * KT;

    if (tid < SBM) rowIdx[tid] = g_idx[m0 + tid];
    __syncthreads();

    // A loader: 64 rows x 32 halves = 256 chunks of 8 halves; 2 chunks/thread,
    // same row: row = tid>>1 (0..63), cols (tid&1)*16 + {0,8}
    const int aRow  = tid >> 1;
    const int aCol0 = (tid & 1) * 16;
    const __half* aSrc = g_adj16 + (size_t)rowIdx[aRow] * N_NODES + aCol0;

    // B loader: 32 rows x 64 halves = 256 chunks; 2 chunks/thread:
    // chunk = tid*2+j -> row = chunk>>3, col = (chunk&7)*8
    auto load_stage = [&](int kt, int s) {
        const int k0 = (kbase + kt) * SBK;
        cp16(&As[s][aRow][aCol0],     aSrc + k0);
        cp16(&As[s][aRow][aCol0 + 8], aSrc + k0 + 8);
#pragma unroll
        for (int j = 0; j < 2; j++) {
            int chunk = tid * 2 + j;
            int br = chunk >> 3;
            int bc = (chunk & 7) * 8;
            cp16(&Bs[s][br][bc], g_y16 + (size_t)(k0 + br) * UNITS + n0 + bc);
        }
    };

    float acc[2][4][4];
#pragma unroll
    for (int mf = 0; mf < 2; mf++)
#pragma unroll
        for (int nf = 0; nf < 4; nf++)
#pragma unroll
            for (int e = 0; e < 4; e++) acc[mf][nf][e] = 0.f;

    // 3-stage pipeline: prologue fills stages 0,1; loop keeps 2-deep lookahead.
    load_stage(0, 0); CP_COMMIT();
    load_stage(1, 1); CP_COMMIT();
    for (int kt = 0; kt < KT; ++kt) {
        CP_WAIT(1);            // stage kt drained (only stage kt+1's group may pend)
        __syncthreads();       // RAW for stage kt; WAR for buffer (kt+2)%3 (=kt-1's)
        if (kt + 2 < KT) load_stage(kt + 2, (kt + 2) % SSTG);
        CP_COMMIT();
        GEMM_COMPUTE(As, Bs, kt % SSTG, 2)
    }

    // write raw partials
    float* part = g_part + (size_t)z * N_GATHER * UNITS;
    const int groupID = lane >> 2;
    const int tid4    = lane & 3;
#pragma unroll
    for (int mf = 0; mf < 2; mf++) {
#pragma unroll
        for (int nf = 0; nf < 4; nf++) {
            int c = n0 + warpN * 32 + nf * 8 + tid4 * 2;
#pragma unroll
            for (int h = 0; h < 2; h++) {
                int g = m0 + warpM * 32 + mf * 16 + groupID + h * 8;
                part[(size_t)g * UNITS + c]     = acc[mf][nf][h * 2 + 0];
                part[(size_t)g * UNITS + c + 1] = acc[mf][nf][h * 2 + 1];
            }
        }
    }
}

// ---------------------------------------------------------------------------
// K4: reduce splits + epilogue.
// out[g,c] = relu( d_i * ( sum_z part[z][g][c] + y32[i][c] ) + bias[c] )
// ---------------------------------------------------------------------------
__global__ void __launch_bounds__(256) k_reduce(const float* __restrict__ bias,
                                                float* __restrict__ out)
{
    const int t  = blockIdx.x * 256 + threadIdx.x;   // 0 .. 4096*64-1
    const int g  = t >> 6;
    const int c  = (t & 63) * 4;
    const int i  = g_idx[g];
    const float di = g_d[i];

    float4 s = *reinterpret_cast<const float4*>(&g_part[(size_t)g * UNITS + c]);
#pragma unroll
    for (int z = 1; z < SPLITS; z++) {
        const float4 p = *reinterpret_cast<const float4*>(
            &g_part[(size_t)z * N_GATHER * UNITS + (size_t)g * UNITS + c]);
        s.x += p.x; s.y += p.y; s.z += p.z; s.w += p.w;
    }
    const float4 y = *reinterpret_cast<const float4*>(&g_y32[(size_t)i * UNITS + c]);
    const float4 b = *reinterpret_cast<const float4*>(&bias[c]);

    float4 r;
    r.x = fmaxf(di * (s.x + y.x) + b.x, 0.f);
    r.y = fmaxf(di * (s.y + y.y) + b.y, 0.f);
    r.z = fmaxf(di * (s.z + y.z) + b.z, 0.f);
    r.w = fmaxf(di * (s.w + y.w) + b.w, 0.f);
    *reinterpret_cast<float4*>(&out[(size_t)g * UNITS + c]) = r;
}

// ---------------------------------------------------------------------------
// Launch — inputs resolved BY ELEMENT COUNT (order-proof)
// ---------------------------------------------------------------------------
extern "C" void kernel_launch(void* const* d_in, const int* in_sizes, int n_in,
                              void* d_out, int out_size)
{
    (void)out_size;
    const float* adj    = nullptr;
    const int*   gather = nullptr;
    const float* feat   = nullptr;
    const float* wk     = nullptr;
    const float* bias   = nullptr;

    for (int i = 0; i < n_in; i++) {
        switch (in_sizes[i]) {
            case 67108864: adj    = (const float*)d_in[i]; break;
            case 4096:     gather = (const int*)d_in[i];   break;
            case 4194304:  feat   = (const float*)d_in[i]; break;
            case 131072:   wk     = (const float*)d_in[i]; break;
            case 256:      bias   = (const float*)d_in[i]; break;
            default: break;
        }
    }
    float* out = (float*)d_out;

    k_gather_prep<<<1, 256>>>(gather);
    k_cvt<<<4096 + 128, 256>>>(feat, wk);
    k_rowsum16<<<N_NODES, 256>>>(adj);
    k_xw16<<<dim3(N_NODES / GBM, UNITS / GBN), 128>>>();
    k_spmm16_split<<<dim3(N_GATHER / SBM, UNITS / SBN, SPLITS), 128>>>();
    k_reduce<<<(N_GATHER * UNITS / 4) / 256, 256>>>(bias, out);
}

// round 16
// speedup vs baseline: 1.2371x; 1.1314x over previous
#include <cuda_runtime.h>
#include <cuda_fp16.h>
#include <cstdint>
#include <cstddef>

#define N_NODES 8192
#define F_DIM 512
#define UNITS 256
#define N_GATHER 4096
#define SPLITS 4

// Device-global scratch (no allocation allowed)
__device__ __align__(16) float  g_d[N_NODES];                    // 32 KB
__device__ __align__(16) float  g_y32[N_NODES * UNITS];          // 8 MB
__device__ __align__(16) __half g_y16[N_NODES * UNITS];          // 4 MB
__device__ __align__(16) __half g_f16[N_NODES * F_DIM];          // 8 MB
__device__ __align__(16) __half g_w16[F_DIM * UNITS];            // 256 KB
__device__ __align__(16) __half g_adj16[(size_t)N_NODES * N_NODES]; // 128 MB
__device__ __align__(16) float  g_part[(size_t)SPLITS * N_GATHER * UNITS]; // 16 MB
__device__ __align__(16) int    g_idx[N_GATHER];
__device__               int    g_rowflag[N_NODES];

// ---------------------------------------------------------------------------
// helpers
// ---------------------------------------------------------------------------
__device__ __forceinline__ uint32_t f2h2(float a, float b)
{
    __half2 h = __floats2half2_rn(a, b);
    return *reinterpret_cast<uint32_t*>(&h);
}
__device__ __forceinline__ uint32_t smem_u32(const void* p)
{
    return (uint32_t)__cvta_generic_to_shared(p);
}
__device__ __forceinline__ void cp16(void* sdst, const void* gsrc)
{
    asm volatile("cp.async.cg.shared.global [%0], [%1], 16;"
                 :: "r"(smem_u32(sdst)), "l"(gsrc));
}
#define CP_COMMIT() asm volatile("cp.async.commit_group;" ::)
#define CP_WAIT(n)  asm volatile("cp.async.wait_group %0;" :: "n"(n))

__device__ __forceinline__ void ldsm_x4(uint32_t& r0, uint32_t& r1, uint32_t& r2, uint32_t& r3,
                                        uint32_t a)
{
    asm volatile("ldmatrix.sync.aligned.m8n8.x4.shared.b16 {%0,%1,%2,%3}, [%4];"
                 : "=r"(r0), "=r"(r1), "=r"(r2), "=r"(r3) : "r"(a));
}
__device__ __forceinline__ void ldsm_x4_t(uint32_t& r0, uint32_t& r1, uint32_t& r2, uint32_t& r3,
                                          uint32_t a)
{
    asm volatile("ldmatrix.sync.aligned.m8n8.x4.trans.shared.b16 {%0,%1,%2,%3}, [%4];"
                 : "=r"(r0), "=r"(r1), "=r"(r2), "=r"(r3) : "r"(a));
}
__device__ __forceinline__ void mma16816(float* c,
                                         uint32_t a0, uint32_t a1, uint32_t a2, uint32_t a3,
                                         uint32_t b0, uint32_t b1)
{
    asm volatile(
        "mma.sync.aligned.m16n8k16.row.col.f32.f16.f16.f32 "
        "{%0,%1,%2,%3}, {%4,%5,%6,%7}, {%8,%9}, {%0,%1,%2,%3};"
        : "+f"(c[0]), "+f"(c[1]), "+f"(c[2]), "+f"(c[3])
        : "r"(a0), "r"(a1), "r"(a2), "r"(a3), "r"(b0), "r"(b1));
}

// ---------------------------------------------------------------------------
// K0: dtype-agnostic gather expansion + gathered-row bitmap.
// ---------------------------------------------------------------------------
__global__ void __launch_bounds__(256) k_gather_prep(const int* __restrict__ gather_raw)
{
    for (int r = threadIdx.x; r < N_NODES; r += 256) g_rowflag[r] = 0;
    __syncthreads();

    __shared__ int is64;
    if (threadIdx.x == 0) {
        int odd_or = 0;
#pragma unroll
        for (int w = 1; w < 16; w += 2) odd_or |= gather_raw[w];
        is64 = (odd_or == 0) ? 1 : 0;
    }
    __syncthreads();
    const int w64 = is64;
    for (int g = threadIdx.x; g < N_GATHER; g += 256) {
        int idx = w64 ? gather_raw[g * 2] : gather_raw[g];
        idx = idx < 0 ? 0 : (idx >= N_NODES ? N_NODES - 1 : idx);
        g_idx[g] = idx;
        g_rowflag[idx] = 1;
    }
}

// ---------------------------------------------------------------------------
// K0b: transcode features and kernel to fp16.
// ---------------------------------------------------------------------------
__global__ void __launch_bounds__(256) k_cvt(const float* __restrict__ feat,
                                             const float* __restrict__ wk)
{
    int b = blockIdx.x;
    if (b < 4096) {
        int base = b * 1024 + threadIdx.x * 4;
        float4 v = *reinterpret_cast<const float4*>(feat + base);
        uint2 w;
        w.x = f2h2(v.x, v.y);
        w.y = f2h2(v.z, v.w);
        *reinterpret_cast<uint2*>(&g_f16[base]) = w;
    } else {
        int base = (b - 4096) * 1024 + threadIdx.x * 4;
        float4 v = *reinterpret_cast<const float4*>(wk + base);
        uint2 w;
        w.x = f2h2(v.x, v.y);
        w.y = f2h2(v.z, v.w);
        *reinterpret_cast<uint2*>(&g_w16[base]) = w;
    }
}

// ---------------------------------------------------------------------------
// K1: rowsum -> d[i] = rsqrt(sum+1); fp16 transcode ONLY for gathered rows.
// ---------------------------------------------------------------------------
__global__ void __launch_bounds__(256) k_rowsum16(const float* __restrict__ adj)
{
    const int row = blockIdx.x;
    const bool wr = (g_rowflag[row] != 0);
    const float4* p = reinterpret_cast<const float4*>(adj + (size_t)row * N_NODES);
    uint2* q = reinterpret_cast<uint2*>(&g_adj16[(size_t)row * N_NODES]);
    float s = 0.f;
    if (wr) {
#pragma unroll 4
        for (int j = threadIdx.x; j < N_NODES / 4; j += 256) {
            float4 v = p[j];
            s += (v.x + v.y) + (v.z + v.w);
            uint2 w;
            w.x = f2h2(v.x, v.y);
            w.y = f2h2(v.z, v.w);
            q[j] = w;
        }
    } else {
#pragma unroll 4
        for (int j = threadIdx.x; j < N_NODES / 4; j += 256) {
            float4 v = p[j];
            s += (v.x + v.y) + (v.z + v.w);
        }
    }
#pragma unroll
    for (int o = 16; o > 0; o >>= 1) s += __shfl_xor_sync(0xffffffffu, s, o);
    __shared__ float ws[8];
    if ((threadIdx.x & 31) == 0) ws[threadIdx.x >> 5] = s;
    __syncthreads();
    if (threadIdx.x == 0) {
        float t = 0.f;
#pragma unroll
        for (int w = 0; w < 8; w++) t += ws[w];
        g_d[row] = rsqrtf(t + 1.0f);
    }
}

// ---------------------------------------------------------------------------
// GEMM geometry: BM=64, BN=64, BK=64, 128 threads (4 warps, 32x32 each),
// 2-stage double buffer (the proven 157.0 configuration), now with
// FRAGMENT DOUBLE-BUFFERING: load slab ks+1's ldmatrix fragments while
// issuing slab ks's MMAs, overlapping LDS latency with tensor issue.
// ---------------------------------------------------------------------------
#define GBM 64
#define GBN 64
#define GBK 64
#define GSTG 2
#define GAS 72
#define GBS 72

#define LOAD_FRAGS(As_, Bs_, s_, ks_, fb_)                                          \
    {                                                                               \
        _Pragma("unroll")                                                           \
        for (int mf = 0; mf < 2; mf++) {                                            \
            int r = warpM * 32 + mf * 16 + (lane & 15);                             \
            int c = (ks_) * 16 + ((lane >> 4) << 3);                                \
            ldsm_x4(af[fb_][mf][0], af[fb_][mf][1], af[fb_][mf][2], af[fb_][mf][3], \
                    smem_u32(&As_[s_][r][c]));                                      \
        }                                                                           \
        _Pragma("unroll")                                                           \
        for (int ng = 0; ng < 2; ng++) {                                            \
            int r = (ks_) * 16 + (lane & 15);                                       \
            int c = warpN * 32 + ng * 16 + ((lane >> 4) << 3);                      \
            ldsm_x4_t(bf[fb_][ng][0], bf[fb_][ng][1], bf[fb_][ng][2], bf[fb_][ng][3],\
                      smem_u32(&Bs_[s_][r][c]));                                    \
        }                                                                           \
    }

// compute 4 ks-slabs (BK=64) from stage s_ with fragment pipelining
#define GEMM_COMPUTE(As_, Bs_, s_)                                                  \
    {                                                                               \
        uint32_t af[2][2][4], bf[2][2][4];                                          \
        LOAD_FRAGS(As_, Bs_, s_, 0, 0)                                              \
        _Pragma("unroll")                                                           \
        for (int ks = 0; ks < 4; ++ks) {                                            \
            if (ks + 1 < 4) LOAD_FRAGS(As_, Bs_, s_, ks + 1, (ks + 1) & 1)          \
            const int fb = ks & 1;                                                  \
            _Pragma("unroll")                                                       \
            for (int mf = 0; mf < 2; mf++)                                          \
                _Pragma("unroll")                                                   \
                for (int nf = 0; nf < 4; nf++)                                      \
                    mma16816(acc[mf][nf],                                           \
                             af[fb][mf][0], af[fb][mf][1], af[fb][mf][2], af[fb][mf][3], \
                             bf[fb][nf >> 1][(nf & 1) * 2],                         \
                             bf[fb][nf >> 1][(nf & 1) * 2 + 1]);                    \
        }                                                                           \
    }

// Double-buffer mainloop (WAR sync / always-commit / RAW sync)
#define GEMM_MAINLOOP(KT_)                                                          \
    load_stage(0, 0);                                                               \
    CP_COMMIT();                                                                    \
    for (int kt = 0; kt < (KT_); ++kt) {                                            \
        __syncthreads();                                                            \
        if (kt + 1 < (KT_)) load_stage(kt + 1, (kt + 1) & 1);                       \
        CP_COMMIT();                                                                \
        CP_WAIT(1);                                                                 \
        __syncthreads();                                                            \
        GEMM_COMPUTE(As, Bs, kt & 1)                                                \
    }

// ---------------------------------------------------------------------------
// K2: y = diag(d) * (f16 @ w16)  -> g_y32 + g_y16.  KT = 8.
// ---------------------------------------------------------------------------
__global__ void __launch_bounds__(128) k_xw16()
{
    __shared__ __align__(16) __half As[GSTG][GBM][GAS];
    __shared__ __align__(16) __half Bs[GSTG][GBK][GBS];

    const int tid   = threadIdx.x;
    const int lane  = tid & 31;
    const int warp  = tid >> 5;
    const int warpM = warp >> 1;
    const int warpN = warp & 1;
    const int r0 = blockIdx.x * GBM;
    const int c0 = blockIdx.y * GBN;
    const int KT = F_DIM / GBK;   // 8

    const int lr = tid >> 3;
    const int lc = (tid & 7) * 8;

    auto load_stage = [&](int kt, int s) {
        const int k0 = kt * GBK;
#pragma unroll
        for (int p = 0; p < 4; p++) {
            int row = lr + p * 16;
            cp16(&As[s][row][lc], g_f16 + (size_t)(r0 + row) * F_DIM + k0 + lc);
        }
#pragma unroll
        for (int p = 0; p < 4; p++) {
            int row = lr + p * 16;
            cp16(&Bs[s][row][lc], g_w16 + (size_t)(k0 + row) * UNITS + c0 + lc);
        }
    };

    float acc[2][4][4];
#pragma unroll
    for (int mf = 0; mf < 2; mf++)
#pragma unroll
        for (int nf = 0; nf < 4; nf++)
#pragma unroll
            for (int e = 0; e < 4; e++) acc[mf][nf][e] = 0.f;

    GEMM_MAINLOOP(KT)

    const int groupID = lane >> 2;
    const int tid4    = lane & 3;
#pragma unroll
    for (int mf = 0; mf < 2; mf++) {
#pragma unroll
        for (int nf = 0; nf < 4; nf++) {
            int c = c0 + warpN * 32 + nf * 8 + tid4 * 2;
#pragma unroll
            for (int h = 0; h < 2; h++) {
                int r = r0 + warpM * 32 + mf * 16 + groupID + h * 8;
                float dr = g_d[r];
                float v0 = dr * acc[mf][nf][h * 2 + 0];
                float v1 = dr * acc[mf][nf][h * 2 + 1];
                g_y32[(size_t)r * UNITS + c]     = v0;
                g_y32[(size_t)r * UNITS + c + 1] = v1;
                *reinterpret_cast<uint32_t*>(&g_y16[(size_t)r * UNITS + c]) = f2h2(v0, v1);
            }
        }
    }
}

// ---------------------------------------------------------------------------
// K3: split-K partial GEMM (the proven 157.0 geometry + fragment pipelining).
// BM=64 x BN=64 x BK=64, 128 threads, 2-stage.  grid (64, 4, SPLITS).
// KT per split = 8192/64/4 = 32.
// ---------------------------------------------------------------------------
__global__ void __launch_bounds__(128) k_spmm16_split()
{
    __shared__ __align__(16) __half As[GSTG][GBM][GAS];
    __shared__ __align__(16) __half Bs[GSTG][GBK][GBS];
    __shared__ int rowIdx[GBM];

    const int tid   = threadIdx.x;
    const int lane  = tid & 31;
    const int warp  = tid >> 5;
    const int warpM = warp >> 1;
    const int warpN = warp & 1;
    const int m0 = blockIdx.x * GBM;
    const int n0 = blockIdx.y * GBN;
    const int z  = blockIdx.z;
    const int KT = N_NODES / GBK / SPLITS;   // 32
    const int kbase = z * KT;

    if (tid < GBM) rowIdx[tid] = g_idx[m0 + tid];
    __syncthreads();

    const int lr = tid >> 3;
    const int lc = (tid & 7) * 8;
    const __half* aSrc[4];
#pragma unroll
    for (int p = 0; p < 4; p++)
        aSrc[p] = g_adj16 + (size_t)rowIdx[lr + p * 16] * N_NODES + lc;

    auto load_stage = [&](int kt, int s) {
        const int k0 = (kbase + kt) * GBK;
#pragma unroll
        for (int p = 0; p < 4; p++)
            cp16(&As[s][lr + p * 16][lc], aSrc[p] + k0);
#pragma unroll
        for (int p = 0; p < 4; p++) {
            int row = lr + p * 16;
            cp16(&Bs[s][row][lc], g_y16 + (size_t)(k0 + row) * UNITS + n0 + lc);
        }
    };

    float acc[2][4][4];
#pragma unroll
    for (int mf = 0; mf < 2; mf++)
#pragma unroll
        for (int nf = 0; nf < 4; nf++)
#pragma unroll
            for (int e = 0; e < 4; e++) acc[mf][nf][e] = 0.f;

    GEMM_MAINLOOP(KT)

    // write raw partials
    float* part = g_part + (size_t)z * N_GATHER * UNITS;
    const int groupID = lane >> 2;
    const int tid4    = lane & 3;
#pragma unroll
    for (int mf = 0; mf < 2; mf++) {
#pragma unroll
        for (int nf = 0; nf < 4; nf++) {
            int c = n0 + warpN * 32 + nf * 8 + tid4 * 2;
#pragma unroll
            for (int h = 0; h < 2; h++) {
                int g = m0 + warpM * 32 + mf * 16 + groupID + h * 8;
                part[(size_t)g * UNITS + c]     = acc[mf][nf][h * 2 + 0];
                part[(size_t)g * UNITS + c + 1] = acc[mf][nf][h * 2 + 1];
            }
        }
    }
}

// ---------------------------------------------------------------------------
// K4: reduce splits + epilogue.
// out[g,c] = relu( d_i * ( sum_z part[z][g][c] + y32[i][c] ) + bias[c] )
// ---------------------------------------------------------------------------
__global__ void __launch_bounds__(256) k_reduce(const float* __restrict__ bias,
                                                float* __restrict__ out)
{
    const int t  = blockIdx.x * 256 + threadIdx.x;   // 0 .. 4096*64-1
    const int g  = t >> 6;
    const int c  = (t & 63) * 4;
    const int i  = g_idx[g];
    const float di = g_d[i];

    float4 s = *reinterpret_cast<const float4*>(&g_part[(size_t)g * UNITS + c]);
#pragma unroll
    for (int z = 1; z < SPLITS; z++) {
        const float4 p = *reinterpret_cast<const float4*>(
            &g_part[(size_t)z * N_GATHER * UNITS + (size_t)g * UNITS + c]);
        s.x += p.x; s.y += p.y; s.z += p.z; s.w += p.w;
    }
    const float4 y = *reinterpret_cast<const float4*>(&g_y32[(size_t)i * UNITS + c]);
    const float4 b = *reinterpret_cast<const float4*>(&bias[c]);

    float4 r;
    r.x = fmaxf(di * (s.x + y.x) + b.x, 0.f);
    r.y = fmaxf(di * (s.y + y.y) + b.y, 0.f);
    r.z = fmaxf(di * (s.z + y.z) + b.z, 0.f);
    r.w = fmaxf(di * (s.w + y.w) + b.w, 0.f);
    *reinterpret_cast<float4*>(&out[(size_t)g * UNITS + c]) = r;
}

// ---------------------------------------------------------------------------
// Launch — inputs resolved BY ELEMENT COUNT (order-proof)
// ---------------------------------------------------------------------------
extern "C" void kernel_launch(void* const* d_in, const int* in_sizes, int n_in,
                              void* d_out, int out_size)
{
    (void)out_size;
    const float* adj    = nullptr;
    const int*   gather = nullptr;
    const float* feat   = nullptr;
    const float* wk     = nullptr;
    const float* bias   = nullptr;

    for (int i = 0; i < n_in; i++) {
        switch (in_sizes[i]) {
            case 67108864: adj    = (const float*)d_in[i]; break;
            case 4096:     gather = (const int*)d_in[i];   break;
            case 4194304:  feat   = (const float*)d_in[i]; break;
            case 131072:   wk     = (const float*)d_in[i]; break;
            case 256:      bias   = (const float*)d_in[i]; break;
            default: break;
        }
    }
    float* out = (float*)d_out;

    k_gather_prep<<<1, 256>>>(gather);
    k_cvt<<<4096 + 128, 256>>>(feat, wk);
    k_rowsum16<<<N_NODES, 256>>>(adj);
    k_xw16<<<dim3(N_NODES / GBM, UNITS / GBN), 128>>>();
    k_spmm16_split<<<dim3(N_GATHER / GBM, UNITS / GBN, SPLITS), 128>>>();
    k_reduce<<<(N_GATHER * UNITS / 4) / 256, 256>>>(bias, out);
}

// round 17
// speedup vs baseline: 1.3620x; 1.1010x over previous
#include <cuda_runtime.h>
#include <cuda_fp16.h>
#include <cstdint>
#include <cstddef>

#define N_NODES 8192
#define F_DIM 512
#define UNITS 256
#define N_GATHER 4096
#define SPLITS 4

// Device-global scratch (no allocation allowed)
__device__ __align__(16) float  g_d[N_NODES];                    // 32 KB
__device__ __align__(16) float  g_y32[N_NODES * UNITS];          // 8 MB
__device__ __align__(16) __half g_y16[N_NODES * UNITS];          // 4 MB
__device__ __align__(16) __half g_f16[N_NODES * F_DIM];          // 8 MB
__device__ __align__(16) __half g_w16[F_DIM * UNITS];            // 256 KB
__device__ __align__(16) __half g_adj16[(size_t)N_NODES * N_NODES]; // 128 MB
__device__ __align__(16) float  g_part[(size_t)SPLITS * N_GATHER * UNITS]; // 16 MB
__device__ __align__(16) int    g_idx[N_GATHER];
__device__               int    g_rowflag[N_NODES];

// ---------------------------------------------------------------------------
// helpers
// ---------------------------------------------------------------------------
__device__ __forceinline__ uint32_t f2h2(float a, float b)
{
    __half2 h = __floats2half2_rn(a, b);
    return *reinterpret_cast<uint32_t*>(&h);
}
__device__ __forceinline__ uint32_t smem_u32(const void* p)
{
    return (uint32_t)__cvta_generic_to_shared(p);
}
__device__ __forceinline__ uint32_t sw128(uint32_t off)   // SW128: XOR bits[4:6] with row&7
{
    return off ^ ((off >> 3) & 0x70);
}
__device__ __forceinline__ void cp16(void* sdst, const void* gsrc)
{
    asm volatile("cp.async.cg.shared.global [%0], [%1], 16;"
                 :: "r"(smem_u32(sdst)), "l"(gsrc));
}
__device__ __forceinline__ void cp16_sa(uint32_t sdst, const void* gsrc)
{
    asm volatile("cp.async.cg.shared.global [%0], [%1], 16;"
                 :: "r"(sdst), "l"(gsrc));
}
#define CP_COMMIT() asm volatile("cp.async.commit_group;" ::)
#define CP_WAIT(n)  asm volatile("cp.async.wait_group %0;" :: "n"(n))

__device__ __forceinline__ void ldsm_x4(uint32_t& r0, uint32_t& r1, uint32_t& r2, uint32_t& r3,
                                        uint32_t a)
{
    asm volatile("ldmatrix.sync.aligned.m8n8.x4.shared.b16 {%0,%1,%2,%3}, [%4];"
                 : "=r"(r0), "=r"(r1), "=r"(r2), "=r"(r3) : "r"(a));
}
__device__ __forceinline__ void ldsm_x4_t(uint32_t& r0, uint32_t& r1, uint32_t& r2, uint32_t& r3,
                                          uint32_t a)
{
    asm volatile("ldmatrix.sync.aligned.m8n8.x4.trans.shared.b16 {%0,%1,%2,%3}, [%4];"
                 : "=r"(r0), "=r"(r1), "=r"(r2), "=r"(r3) : "r"(a));
}
__device__ __forceinline__ void mma16816(float* c,
                                         uint32_t a0, uint32_t a1, uint32_t a2, uint32_t a3,
                                         uint32_t b0, uint32_t b1)
{
    asm volatile(
        "mma.sync.aligned.m16n8k16.row.col.f32.f16.f16.f32 "
        "{%0,%1,%2,%3}, {%4,%5,%6,%7}, {%8,%9}, {%0,%1,%2,%3};"
        : "+f"(c[0]), "+f"(c[1]), "+f"(c[2]), "+f"(c[3])
        : "r"(a0), "r"(a1), "r"(a2), "r"(a3), "r"(b0), "r"(b1));
}

// ---------------------------------------------------------------------------
// K0: dtype-agnostic gather expansion + gathered-row bitmap.
// ---------------------------------------------------------------------------
__global__ void __launch_bounds__(256) k_gather_prep(const int* __restrict__ gather_raw)
{
    for (int r = threadIdx.x; r < N_NODES; r += 256) g_rowflag[r] = 0;
    __syncthreads();

    __shared__ int is64;
    if (threadIdx.x == 0) {
        int odd_or = 0;
#pragma unroll
        for (int w = 1; w < 16; w += 2) odd_or |= gather_raw[w];
        is64 = (odd_or == 0) ? 1 : 0;
    }
    __syncthreads();
    const int w64 = is64;
    for (int g = threadIdx.x; g < N_GATHER; g += 256) {
        int idx = w64 ? gather_raw[g * 2] : gather_raw[g];
        idx = idx < 0 ? 0 : (idx >= N_NODES ? N_NODES - 1 : idx);
        g_idx[g] = idx;
        g_rowflag[idx] = 1;
    }
}

// ---------------------------------------------------------------------------
// K0b: transcode features and kernel to fp16.
// ---------------------------------------------------------------------------
__global__ void __launch_bounds__(256) k_cvt(const float* __restrict__ feat,
                                             const float* __restrict__ wk)
{
    int b = blockIdx.x;
    if (b < 4096) {
        int base = b * 1024 + threadIdx.x * 4;
        float4 v = *reinterpret_cast<const float4*>(feat + base);
        uint2 w;
        w.x = f2h2(v.x, v.y);
        w.y = f2h2(v.z, v.w);
        *reinterpret_cast<uint2*>(&g_f16[base]) = w;
    } else {
        int base = (b - 4096) * 1024 + threadIdx.x * 4;
        float4 v = *reinterpret_cast<const float4*>(wk + base);
        uint2 w;
        w.x = f2h2(v.x, v.y);
        w.y = f2h2(v.z, v.w);
        *reinterpret_cast<uint2*>(&g_w16[base]) = w;
    }
}

// ---------------------------------------------------------------------------
// K1: rowsum -> d[i] = rsqrt(sum+1); fp16 transcode ONLY for gathered rows.
// ---------------------------------------------------------------------------
__global__ void __launch_bounds__(256) k_rowsum16(const float* __restrict__ adj)
{
    const int row = blockIdx.x;
    const bool wr = (g_rowflag[row] != 0);
    const float4* p = reinterpret_cast<const float4*>(adj + (size_t)row * N_NODES);
    uint2* q = reinterpret_cast<uint2*>(&g_adj16[(size_t)row * N_NODES]);
    float s = 0.f;
    if (wr) {
#pragma unroll 4
        for (int j = threadIdx.x; j < N_NODES / 4; j += 256) {
            float4 v = p[j];
            s += (v.x + v.y) + (v.z + v.w);
            uint2 w;
            w.x = f2h2(v.x, v.y);
            w.y = f2h2(v.z, v.w);
            q[j] = w;
        }
    } else {
#pragma unroll 4
        for (int j = threadIdx.x; j < N_NODES / 4; j += 256) {
            float4 v = p[j];
            s += (v.x + v.y) + (v.z + v.w);
        }
    }
#pragma unroll
    for (int o = 16; o > 0; o >>= 1) s += __shfl_xor_sync(0xffffffffu, s, o);
    __shared__ float ws[8];
    if ((threadIdx.x & 31) == 0) ws[threadIdx.x >> 5] = s;
    __syncthreads();
    if (threadIdx.x == 0) {
        float t = 0.f;
#pragma unroll
        for (int w = 0; w < 8; w++) t += ws[w];
        g_d[row] = rsqrtf(t + 1.0f);
    }
}

// ---------------------------------------------------------------------------
// K2: xw GEMM (unchanged from 155.6 run): BM=64,BN=64,BK=64, 128 thr, 2-stage,
// padded smem, fragment double-buffering.
// ---------------------------------------------------------------------------
#define GBM 64
#define GBN 64
#define GBK 64
#define GSTG 2
#define GAS 72
#define GBS 72

#define LOAD_FRAGS(As_, Bs_, s_, ks_, fb_)                                          \
    {                                                                               \
        _Pragma("unroll")                                                           \
        for (int mf = 0; mf < 2; mf++) {                                            \
            int r = warpM * 32 + mf * 16 + (lane & 15);                             \
            int c = (ks_) * 16 + ((lane >> 4) << 3);                                \
            ldsm_x4(af[fb_][mf][0], af[fb_][mf][1], af[fb_][mf][2], af[fb_][mf][3], \
                    smem_u32(&As_[s_][r][c]));                                      \
        }                                                                           \
        _Pragma("unroll")                                                           \
        for (int ng = 0; ng < 2; ng++) {                                            \
            int r = (ks_) * 16 + (lane & 15);                                       \
            int c = warpN * 32 + ng * 16 + ((lane >> 4) << 3);                      \
            ldsm_x4_t(bf[fb_][ng][0], bf[fb_][ng][1], bf[fb_][ng][2], bf[fb_][ng][3],\
                      smem_u32(&Bs_[s_][r][c]));                                    \
        }                                                                           \
    }

#define GEMM_COMPUTE(As_, Bs_, s_)                                                  \
    {                                                                               \
        uint32_t af[2][2][4], bf[2][2][4];                                          \
        LOAD_FRAGS(As_, Bs_, s_, 0, 0)                                              \
        _Pragma("unroll")                                                           \
        for (int ks = 0; ks < 4; ++ks) {                                            \
            if (ks + 1 < 4) LOAD_FRAGS(As_, Bs_, s_, ks + 1, (ks + 1) & 1)          \
            const int fb = ks & 1;                                                  \
            _Pragma("unroll")                                                       \
            for (int mf = 0; mf < 2; mf++)                                          \
                _Pragma("unroll")                                                   \
                for (int nf = 0; nf < 4; nf++)                                      \
                    mma16816(acc[mf][nf],                                           \
                             af[fb][mf][0], af[fb][mf][1], af[fb][mf][2], af[fb][mf][3], \
                             bf[fb][nf >> 1][(nf & 1) * 2],                         \
                             bf[fb][nf >> 1][(nf & 1) * 2 + 1]);                    \
        }                                                                           \
    }

__global__ void __launch_bounds__(128) k_xw16()
{
    __shared__ __align__(16) __half As[GSTG][GBM][GAS];
    __shared__ __align__(16) __half Bs[GSTG][GBK][GBS];

    const int tid   = threadIdx.x;
    const int lane  = tid & 31;
    const int warp  = tid >> 5;
    const int warpM = warp >> 1;
    const int warpN = warp & 1;
    const int r0 = blockIdx.x * GBM;
    const int c0 = blockIdx.y * GBN;
    const int KT = F_DIM / GBK;   // 8

    const int lr = tid >> 3;
    const int lc = (tid & 7) * 8;

    auto load_stage = [&](int kt, int s) {
        const int k0 = kt * GBK;
#pragma unroll
        for (int p = 0; p < 4; p++) {
            int row = lr + p * 16;
            cp16(&As[s][row][lc], g_f16 + (size_t)(r0 + row) * F_DIM + k0 + lc);
        }
#pragma unroll
        for (int p = 0; p < 4; p++) {
            int row = lr + p * 16;
            cp16(&Bs[s][row][lc], g_w16 + (size_t)(k0 + row) * UNITS + c0 + lc);
        }
    };

    float acc[2][4][4];
#pragma unroll
    for (int mf = 0; mf < 2; mf++)
#pragma unroll
        for (int nf = 0; nf < 4; nf++)
#pragma unroll
            for (int e = 0; e < 4; e++) acc[mf][nf][e] = 0.f;

    load_stage(0, 0);
    CP_COMMIT();
    for (int kt = 0; kt < KT; ++kt) {
        __syncthreads();
        if (kt + 1 < KT) load_stage(kt + 1, (kt + 1) & 1);
        CP_COMMIT();
        CP_WAIT(1);
        __syncthreads();
        GEMM_COMPUTE(As, Bs, kt & 1)
    }

    const int groupID = lane >> 2;
    const int tid4    = lane & 3;
#pragma unroll
    for (int mf = 0; mf < 2; mf++) {
#pragma unroll
        for (int nf = 0; nf < 4; nf++) {
            int c = c0 + warpN * 32 + nf * 8 + tid4 * 2;
#pragma unroll
            for (int h = 0; h < 2; h++) {
                int r = r0 + warpM * 32 + mf * 16 + groupID + h * 8;
                float dr = g_d[r];
                float v0 = dr * acc[mf][nf][h * 2 + 0];
                float v1 = dr * acc[mf][nf][h * 2 + 1];
                g_y32[(size_t)r * UNITS + c]     = v0;
                g_y32[(size_t)r * UNITS + c + 1] = v1;
                *reinterpret_cast<uint32_t*>(&g_y16[(size_t)r * UNITS + c]) = f2h2(v0, v1);
            }
        }
    }
}

// ---------------------------------------------------------------------------
// K3: split-K partial GEMM.  BM=64 x BN=64 x BK=64, 128 threads, **3-stage**
// pipeline with XOR-swizzled (SW128) UNPADDED tiles: 3*(8K+8K) = 48 KB exactly.
// No rowIdx smem (epilogue writes raw partials only).  grid (64, 4, SPLITS).
// KT per split = 8192/64/4 = 32.
// ---------------------------------------------------------------------------
#define SSTG 3
#define TILE_B 8192   // one 64x64-half tile in bytes

__global__ void __launch_bounds__(128) k_spmm16_split()
{
    __shared__ __align__(128) __half SA[SSTG * 64 * 64];
    __shared__ __align__(128) __half SB[SSTG * 64 * 64];

    const int tid   = threadIdx.x;
    const int lane  = tid & 31;
    const int warp  = tid >> 5;
    const int warpM = warp >> 1;
    const int warpN = warp & 1;
    const int m0 = blockIdx.x * 64;
    const int n0 = blockIdx.y * 64;
    const int z  = blockIdx.z;
    const int KT = N_NODES / 64 / SPLITS;   // 32
    const int kbase = z * KT;

    const uint32_t sA = smem_u32(SA);
    const uint32_t sB = smem_u32(SB);

    // loader mapping: lr = tid>>3 (0..15), rows lr + p*16; 16B chunk col (tid&7)*16 bytes
    const int lr  = tid >> 3;
    const int lcb = (tid & 7) * 16;          // byte col within 128B row
    const __half* aSrc[4];
#pragma unroll
    for (int p = 0; p < 4; p++) {
        int i = g_idx[m0 + lr + p * 16];
        aSrc[p] = g_adj16 + (size_t)i * N_NODES + (lcb >> 1);
    }

    auto load_stage = [&](int kt, int s) {
        const int k0 = (kbase + kt) * 64;
#pragma unroll
        for (int p = 0; p < 4; p++) {
            int row = lr + p * 16;
            cp16_sa(sA + s * TILE_B + sw128(row * 128 + lcb), aSrc[p] + k0);
        }
#pragma unroll
        for (int p = 0; p < 4; p++) {
            int row = lr + p * 16;
            cp16_sa(sB + s * TILE_B + sw128(row * 128 + lcb),
                    g_y16 + (size_t)(k0 + row) * UNITS + n0 + (lcb >> 1));
        }
    };

    float acc[2][4][4];
#pragma unroll
    for (int mf = 0; mf < 2; mf++)
#pragma unroll
        for (int nf = 0; nf < 4; nf++)
#pragma unroll
            for (int e = 0; e < 4; e++) acc[mf][nf][e] = 0.f;

    // swizzled fragment loads
#define S_LOAD_FRAGS(s_, ks_, fb_)                                                  \
    {                                                                               \
        _Pragma("unroll")                                                           \
        for (int mf = 0; mf < 2; mf++) {                                            \
            int r = warpM * 32 + mf * 16 + (lane & 15);                             \
            int c = (ks_) * 16 + ((lane >> 4) << 3);                                \
            ldsm_x4(af[fb_][mf][0], af[fb_][mf][1], af[fb_][mf][2], af[fb_][mf][3], \
                    sA + (s_) * TILE_B + sw128(r * 128 + c * 2));                   \
        }                                                                           \
        _Pragma("unroll")                                                           \
        for (int ng = 0; ng < 2; ng++) {                                            \
            int r = (ks_) * 16 + (lane & 15);                                       \
            int c = warpN * 32 + ng * 16 + ((lane >> 4) << 3);                      \
            ldsm_x4_t(bf[fb_][ng][0], bf[fb_][ng][1], bf[fb_][ng][2], bf[fb_][ng][3],\
                      sB + (s_) * TILE_B + sw128(r * 128 + c * 2));                 \
        }                                                                           \
    }

    // 3-stage mainloop: barrier per 64-K slab, 2-deep cp.async lookahead.
    load_stage(0, 0); CP_COMMIT();
    load_stage(1, 1); CP_COMMIT();
    for (int kt = 0; kt < KT; ++kt) {
        CP_WAIT(1);           // stage kt drained (only kt+1's group may pend)
        __syncthreads();      // RAW stage kt; WAR buffer (kt+2)%3
        if (kt + 2 < KT) load_stage(kt + 2, (kt + 2) % SSTG);
        CP_COMMIT();
        const int s = kt % SSTG;
        {
            uint32_t af[2][2][4], bf[2][2][4];
            S_LOAD_FRAGS(s, 0, 0)
#pragma unroll
            for (int ks = 0; ks < 4; ++ks) {
                if (ks + 1 < 4) S_LOAD_FRAGS(s, ks + 1, (ks + 1) & 1)
                const int fb = ks & 1;
#pragma unroll
                for (int mf = 0; mf < 2; mf++)
#pragma unroll
                    for (int nf = 0; nf < 4; nf++)
                        mma16816(acc[mf][nf],
                                 af[fb][mf][0], af[fb][mf][1], af[fb][mf][2], af[fb][mf][3],
                                 bf[fb][nf >> 1][(nf & 1) * 2],
                                 bf[fb][nf >> 1][(nf & 1) * 2 + 1]);
            }
        }
    }
#undef S_LOAD_FRAGS

    // write raw partials
    float* part = g_part + (size_t)z * N_GATHER * UNITS;
    const int groupID = lane >> 2;
    const int tid4    = lane & 3;
#pragma unroll
    for (int mf = 0; mf < 2; mf++) {
#pragma unroll
        for (int nf = 0; nf < 4; nf++) {
            int c = n0 + warpN * 32 + nf * 8 + tid4 * 2;
#pragma unroll
            for (int h = 0; h < 2; h++) {
                int g = m0 + warpM * 32 + mf * 16 + groupID + h * 8;
                part[(size_t)g * UNITS + c]     = acc[mf][nf][h * 2 + 0];
                part[(size_t)g * UNITS + c + 1] = acc[mf][nf][h * 2 + 1];
            }
        }
    }
}

// ---------------------------------------------------------------------------
// K4: reduce splits + epilogue.
// out[g,c] = relu( d_i * ( sum_z part[z][g][c] + y32[i][c] ) + bias[c] )
// ---------------------------------------------------------------------------
__global__ void __launch_bounds__(256) k_reduce(const float* __restrict__ bias,
                                                float* __restrict__ out)
{
    const int t  = blockIdx.x * 256 + threadIdx.x;   // 0 .. 4096*64-1
    const int g  = t >> 6;
    const int c  = (t & 63) * 4;
    const int i  = g_idx[g];
    const float di = g_d[i];

    float4 s = *reinterpret_cast<const float4*>(&g_part[(size_t)g * UNITS + c]);
#pragma unroll
    for (int z = 1; z < SPLITS; z++) {
        const float4 p = *reinterpret_cast<const float4*>(
            &g_part[(size_t)z * N_GATHER * UNITS + (size_t)g * UNITS + c]);
        s.x += p.x; s.y += p.y; s.z += p.z; s.w += p.w;
    }
    const float4 y = *reinterpret_cast<const float4*>(&g_y32[(size_t)i * UNITS + c]);
    const float4 b = *reinterpret_cast<const float4*>(&bias[c]);

    float4 r;
    r.x = fmaxf(di * (s.x + y.x) + b.x, 0.f);
    r.y = fmaxf(di * (s.y + y.y) + b.y, 0.f);
    r.z = fmaxf(di * (s.z + y.z) + b.z, 0.f);
    r.w = fmaxf(di * (s.w + y.w) + b.w, 0.f);
    *reinterpret_cast<float4*>(&out[(size_t)g * UNITS + c]) = r;
}

// ---------------------------------------------------------------------------
// Launch — inputs resolved BY ELEMENT COUNT (order-proof)
// ---------------------------------------------------------------------------
extern "C" void kernel_launch(void* const* d_in, const int* in_sizes, int n_in,
                              void* d_out, int out_size)
{
    (void)out_size;
    const float* adj    = nullptr;
    const int*   gather = nullptr;
    const float* feat   = nullptr;
    const float* wk     = nullptr;
    const float* bias   = nullptr;

    for (int i = 0; i < n_in; i++) {
        switch (in_sizes[i]) {
            case 67108864: adj    = (const float*)d_in[i]; break;
            case 4096:     gather = (const int*)d_in[i];   break;
            case 4194304:  feat   = (const float*)d_in[i]; break;
            case 131072:   wk     = (const float*)d_in[i]; break;
            case 256:      bias   = (const float*)d_in[i]; break;
            default: break;
        }
    }
    float* out = (float*)d_out;

    k_gather_prep<<<1, 256>>>(gather);
    k_cvt<<<4096 + 128, 256>>>(feat, wk);
    k_rowsum16<<<N_NODES, 256>>>(adj);
    k_xw16<<<dim3(N_NODES / GBM, UNITS / GBN), 128>>>();
    k_spmm16_split<<<dim3(N_GATHER / 64, UNITS / 64, SPLITS), 128>>>();
    k_reduce<<<(N_GATHER * UNITS / 4) / 256, 256>>>(bias, out);
}